// round 9
// baseline (speedup 1.0000x reference)
#include <cuda_runtime.h>
#include <cuda_bf16.h>
#include <cstdint>
#include <cstddef>

#define Hdim 1024
#define Edim 18432
#define Vdim 32000
#define Tlen 15

struct State {
    float feat[Hdim];
    float h[Hdim], c[Hdim];
    float tmph[Hdim], tmpc[Hdim];
    float h1[Hdim], c1[Hdim];
    float h2[2][Hdim], c2[2][Hdim];
    float h3[2][Hdim], c3[2][Hdim];
    float word[Hdim];
    float hi[Vdim];
    unsigned long long lomax, exmax;
    unsigned ticket1, ticket3;
};
__device__ State g_s;
__device__ unsigned g_fcw8[(size_t)Vdim * (Hdim / 4)];  // int8-packed fc_w (32.8 MB)
__device__ float g_scale[Vdim];
__device__ float g_sumw[Vdim];
__device__ unsigned g_pc[4];                             // phase counters (reset each step)

// ---------- helpers ----------
__device__ __forceinline__ float sigf(float x) { return 1.0f / (1.0f + expf(-x)); }

__device__ __forceinline__ void pf_l2(const void* p) {
    asm volatile("prefetch.global.L2 [%0];" :: "l"(p));
}

__device__ __forceinline__ float warp_sum(float s) {
#pragma unroll
    for (int o = 16; o; o >>= 1) s += __shfl_xor_sync(0xffffffffu, s, o);
    return s;
}
__device__ __forceinline__ int warp_isum(int s) {
#pragma unroll
    for (int o = 16; o; o >>= 1) s += __shfl_xor_sync(0xffffffffu, s, o);
    return s;
}
__device__ __forceinline__ float warp_max(float s) {
#pragma unroll
    for (int o = 16; o; o >>= 1) s = fmaxf(s, __shfl_xor_sync(0xffffffffu, s, o));
    return s;
}

__device__ __forceinline__ float block_sum(float s) {
    __shared__ float sm[8];
    __shared__ float outv;
    int w = threadIdx.x >> 5, lane = threadIdx.x & 31;
    s = warp_sum(s);
    if (lane == 0) sm[w] = s;
    __syncthreads();
    if (w == 0) {
        float r = (lane < 8) ? sm[lane] : 0.0f;
        r = warp_sum(r);
        if (lane == 0) outv = r;
    }
    __syncthreads();
    float res = outv;
    __syncthreads();
    return res;
}

__device__ __forceinline__ unsigned long long packkey(float v, unsigned idx) {
    unsigned u = __float_as_uint(v);
    u = (u & 0x80000000u) ? ~u : (u | 0x80000000u);
    return ((unsigned long long)u << 32) | (unsigned long long)(0xFFFFFFFFu - idx);
}
__device__ __forceinline__ float key_val(unsigned long long k) {
    unsigned u = (unsigned)(k >> 32);
    u = (u & 0x80000000u) ? (u ^ 0x80000000u) : ~u;
    return __uint_as_float(u);
}
__device__ __forceinline__ int key_idx(unsigned long long k) {
    return (int)(0xFFFFFFFFu - (unsigned)(k & 0xFFFFFFFFull));
}

__device__ __forceinline__ int clamp127(int q) {
    return q < -127 ? -127 : (q > 127 ? 127 : q);
}
__device__ __forceinline__ unsigned pack4(float4 f, float inv) {
    int a = clamp127(__float2int_rn(f.x * inv));
    int b = clamp127(__float2int_rn(f.y * inv));
    int c = clamp127(__float2int_rn(f.z * inv));
    int d = clamp127(__float2int_rn(f.w * inv));
    return (a & 0xFF) | ((b & 0xFF) << 8) | ((c & 0xFF) << 16) | ((d & 0xFF) << 24);
}

// ---------- phase sync (block-order pipeline) ----------
__device__ __forceinline__ void phase_wait(unsigned* c, unsigned target) {
    if (threadIdx.x == 0) {
        volatile unsigned* vc = (volatile unsigned*)c;
        while (*vc < target) __nanosleep(64);
    }
    __syncthreads();
}
__device__ __forceinline__ void phase_done(unsigned* c) {
    __threadfence();
    __syncthreads();
    if (threadIdx.x == 0) atomicAdd(c, 1u);
}

// ---------- LayerNorm over 1024 elems by one 256-thread block (x via L2) ----------
__device__ void ln256(const float* __restrict__ x, const float* __restrict__ g,
                      const float* __restrict__ b, const float* __restrict__ base,
                      float* __restrict__ o) {
    float xv[4];
    float s = 0.f;
#pragma unroll
    for (int k = 0; k < 4; k++) { xv[k] = __ldcg(&x[threadIdx.x + 256 * k]); s += xv[k]; }
    float m = block_sum(s) * (1.f / Hdim);
    float q = 0.f;
#pragma unroll
    for (int k = 0; k < 4; k++) { float d = xv[k] - m; q += d * d; }
    float v = block_sum(q) * (1.f / Hdim);
    float inv = rsqrtf(v + 1e-5f);
#pragma unroll
    for (int k = 0; k < 4; k++) {
        int i = threadIdx.x + 256 * k;
        float r = (xv[k] - m) * inv * g[i] + b[i];
        if (base) r += base[i];
        o[i] = r;
    }
}

// ---------- LSTM cell body (8 warps; 0-3 W_ih gates, 4-7 W_hh gates) ----------
// Prefetches its weight rows to L2, then waits on wc (if non-null), then computes.
__device__ __forceinline__ void cell_body(
    int j,
    const float* __restrict__ x, const float* __restrict__ hin, const float* __restrict__ cin,
    const float* __restrict__ wih, const float* __restrict__ whh,
    const float* __restrict__ bih, const float* __restrict__ bhh,
    float* __restrict__ hout, float* __restrict__ cout,
    unsigned* wc, unsigned wtarget) {
    int w = threadIdx.x >> 5, lane = threadIdx.x & 31;
    const float* Wm  = (w < 4) ? wih : whh;
    const float* vec = (w < 4) ? x : hin;
    int row = j + (w & 3) * Hdim;
    const float4* Wr = (const float4*)(Wm + (size_t)row * Hdim);
    pf_l2((const char*)Wr + lane * 128);   // warm L2 while predecessor phase runs
    if (wc) phase_wait(wc, wtarget);
    float s = 0.f;
#pragma unroll
    for (int i = 0; i < 8; i++) {
        float4 a = Wr[lane + 32 * i];
        float4 b = __ldcg((const float4*)vec + lane + 32 * i);
        s += a.x * b.x + a.y * b.y + a.z * b.z + a.w * b.w;
    }
    s = warp_sum(s);
    __shared__ float red[8];
    if (lane == 0) red[w] = s;
    __syncthreads();
    if (threadIdx.x == 0) {
        float gi = red[0] + red[4] + bih[j]            + bhh[j];
        float gf = red[1] + red[5] + bih[j + Hdim]     + bhh[j + Hdim];
        float gg = red[2] + red[6] + bih[j + 2 * Hdim] + bhh[j + 2 * Hdim];
        float go = red[3] + red[7] + bih[j + 3 * Hdim] + bhh[j + 3 * Hdim];
        float cn = sigf(gf) * __ldcg(&cin[j]) + sigf(gi) * tanhf(gg);
        cout[j] = cn;
        hout[j] = sigf(go) * tanhf(cn);
    }
}

// ---------- prologue: fc1 rows (blocks < Hdim) + int8 quantize fc_w (rest) ----------
__global__ void __launch_bounds__(256) k_pro1(
    const float* __restrict__ feats, const float* __restrict__ w,
    const float* __restrict__ bias, const float* __restrict__ fcw32) {
    int wid = threadIdx.x >> 5, lane = threadIdx.x & 31;
    if (blockIdx.x < Hdim) {
        int j = blockIdx.x;
        const float4* Wr = (const float4*)(w + (size_t)j * Edim);
        const float4* X  = (const float4*)feats;
        float s = 0.f;
        for (int i = threadIdx.x; i < Edim / 4; i += 256) {
            float4 a = __ldcs(&Wr[i]), v = X[i];
            s += a.x * v.x + a.y * v.y + a.z * v.z + a.w * v.w;
        }
        s = block_sum(s);
        if (threadIdx.x == 0) g_s.feat[j] = fmaxf(s + bias[j], 0.f);
    } else {
        int r = (blockIdx.x - Hdim) * 8 + wid;
        const float4* Wr = (const float4*)(fcw32 + (size_t)r * Hdim);
        float4 v[8];
        float ma = 0.f, sa = 0.f;
#pragma unroll
        for (int k = 0; k < 8; k++) {
            v[k] = __ldcs(&Wr[lane + 32 * k]);
            ma = fmaxf(ma, fmaxf(fmaxf(fabsf(v[k].x), fabsf(v[k].y)),
                                 fmaxf(fabsf(v[k].z), fabsf(v[k].w))));
            sa += fabsf(v[k].x) + fabsf(v[k].y) + fabsf(v[k].z) + fabsf(v[k].w);
        }
        ma = warp_max(ma);
        sa = warp_sum(sa);
        float mg = fmaxf(ma, 1e-30f);
        float s = mg * (1.f / 127.f);
        float inv = 127.f / mg;
        unsigned* W8 = g_fcw8 + (size_t)r * (Hdim / 4);
#pragma unroll
        for (int k = 0; k < 8; k++) W8[lane + 32 * k] = pack4(v[k], inv);
        if (lane == 0) { g_scale[r] = s; g_sumw[r] = sa; }
    }
}

// ---------- init h/c GEMVs + (last block) prologue LayerNorms ----------
__global__ void __launch_bounds__(256) k_init2(
    const float* __restrict__ wh, const float* __restrict__ bh,
    const float* __restrict__ wc, const float* __restrict__ bc,
    const float* __restrict__ lnhg, const float* __restrict__ lnhb,
    const float* __restrict__ lncg, const float* __restrict__ lncb) {
    int j = blockIdx.x;
    bool ish = j < Hdim;
    int r = ish ? j : j - Hdim;
    const float4* Wr = (const float4*)((ish ? wh : wc) + (size_t)r * Hdim);
    const float4* X  = (const float4*)g_s.feat;
    float4 a = __ldcs(&Wr[threadIdx.x]), v = X[threadIdx.x];
    float s = a.x * v.x + a.y * v.y + a.z * v.z + a.w * v.w;
    s = block_sum(s);
    __shared__ bool lastb;
    if (threadIdx.x == 0) {
        float val = fmaxf(s + (ish ? bh[r] : bc[r]), 0.f);
        if (ish) g_s.tmph[r] = val; else g_s.tmpc[r] = val;
        __threadfence();
        lastb = (atomicAdd(&g_s.ticket1, 1u) == 2u * Hdim - 1u);
    }
    __syncthreads();
    if (!lastb) return;
    ln256(g_s.tmph, lnhg, lnhb, nullptr, g_s.h);
    ln256(g_s.tmpc, lncg, lncb, nullptr, g_s.c);
    if (threadIdx.x == 0) g_s.ticket1 = 0;
}

// ---------- one full decode step: 5 phases in one launch ----------
// [0,1024)      phase1: cell1                       -> c0
// [1024,1026)   LN h / LN c for next step (wait c0) -> c1
// [1026,2050)   phase2: cell2 (wait c0)             -> c1   (c1 target = 1026)
// [2050,3074)   phase3: cell3 (wait c1 == 1026)     -> c2
// [3074,4074)   phase4: fcb8  (wait c2 == 1024)     -> c3
// [4074,4199)   phase5: refine (wait c3 == 1000); last block emits + resets
__global__ void __launch_bounds__(256) k_step(
    const float* __restrict__ x1, const float* __restrict__ h1in, const float* __restrict__ c1in,
    const float* __restrict__ w_ih1, const float* __restrict__ w_hh1,
    const float* __restrict__ b_ih1, const float* __restrict__ b_hh1,
    const float* __restrict__ w_ih2, const float* __restrict__ w_hh2,
    const float* __restrict__ b_ih2, const float* __restrict__ b_hh2,
    const float* __restrict__ h2p, const float* __restrict__ c2p,
    const float* __restrict__ h3p, const float* __restrict__ c3p,
    float* __restrict__ h2q, float* __restrict__ c2q,
    float* __restrict__ h3q, float* __restrict__ c3q,
    const float* __restrict__ lnhg, const float* __restrict__ lnhb,
    const float* __restrict__ lncg, const float* __restrict__ lncb,
    const float* __restrict__ fcb, const float* __restrict__ fcw32,
    const float* __restrict__ embed, const float* __restrict__ tot,
    float* __restrict__ out, int t) {
    int bid = blockIdx.x;
    int tid = threadIdx.x, wid = tid >> 5, lane = tid & 31;

    if (bid < 1024) {
        cell_body(bid, x1, h1in, c1in, w_ih1, w_hh1, b_ih1, b_hh1,
                  g_s.h1, g_s.c1, nullptr, 0);
        phase_done(&g_pc[0]);
        return;
    }
    if (bid < 1026) {   // LayerNorms for the NEXT step
        phase_wait(&g_pc[0], 1024);
        bool ish = (bid == 1024);
        ln256(ish ? g_s.h1 : g_s.c1,
              ish ? lnhg : lncg, ish ? lnhb : lncb,
              ish ? g_s.h : g_s.c,
              ish ? g_s.tmph : g_s.tmpc);
        phase_done(&g_pc[1]);
        return;
    }
    if (bid < 2050) {   // cell2
        cell_body(bid - 1026, g_s.h1, h2p, c2p, w_ih2, w_hh2, b_ih2, b_hh2,
                  h2q, c2q, &g_pc[0], 1024);
        phase_done(&g_pc[1]);
        return;
    }
    if (bid < 3074) {   // cell3
        cell_body(bid - 2050, h2q, h3p, c3p, w_ih2, w_hh2, b_ih2, b_hh2,
                  h3q, c3q, &g_pc[1], 1026);
        phase_done(&g_pc[2]);
        return;
    }
    if (bid < 4074) {   // fcb8: int8 vocab GEMV + interval bound
        int r0 = ((bid - 3074) * 8 + wid) * 4;
        {   // prefetch this warp's 4 int8 rows while cell3 runs
            const char* base = (const char*)(g_fcw8 + (size_t)(r0 + (lane >> 3)) * (Hdim / 4));
            pf_l2(base + (lane & 7) * 128);
        }
        phase_wait(&g_pc[2], 1024);
        const float4* X = (const float4*)h3q;
        float4 xv[8];
        float ma = 0.f, sa = 0.f;
#pragma unroll
        for (int k = 0; k < 8; k++) {
            xv[k] = __ldcg(&X[lane + 32 * k]);
            ma = fmaxf(ma, fmaxf(fmaxf(fabsf(xv[k].x), fabsf(xv[k].y)),
                                 fmaxf(fabsf(xv[k].z), fabsf(xv[k].w))));
            sa += fabsf(xv[k].x) + fabsf(xv[k].y) + fabsf(xv[k].z) + fabsf(xv[k].w);
        }
        ma = warp_max(ma);
        float sumAbsX = warp_sum(sa);
        float mg = fmaxf(ma, 1e-30f);
        float sx = mg * (1.f / 127.f);
        float invx = 127.f / mg;
        unsigned qx[8];
#pragma unroll
        for (int k = 0; k < 8; k++) qx[k] = pack4(xv[k], invx);
        unsigned long long wbest = 0ull;
#pragma unroll
        for (int rr = 0; rr < 4; rr++) {
            int r = r0 + rr;
            const unsigned* W8 = g_fcw8 + (size_t)r * (Hdim / 4);
            int acc = 0;
#pragma unroll
            for (int k = 0; k < 8; k++)
                acc = __dp4a((int)W8[lane + 32 * k], (int)qx[k], acc);
            acc = warp_isum(acc);
            if (lane == 0) {
                float sr = g_scale[r];
                float v = sr * sx * (float)acc + fcb[r];
                float err = (0.5f * sx * g_sumw[r] + 0.5f * sr * (sumAbsX + 512.f * sx)) * 1.1f
                            + 1e-7f;
                g_s.hi[r] = v + err;
                unsigned long long key = packkey(v - err, (unsigned)r);
                if (key > wbest) wbest = key;
            }
        }
        __shared__ unsigned long long sb[8];
        if (lane == 0) sb[wid] = wbest;
        __syncthreads();
        if (tid == 0) {
            unsigned long long m = sb[0];
#pragma unroll
            for (int k = 1; k < 8; k++) if (sb[k] > m) m = sb[k];
            atomicMax(&g_s.lomax, m);
        }
        phase_done(&g_pc[3]);
        return;
    }

    // ---- phase5: refine (exact fp32 re-dot of candidates) ----
    {
        int rb = bid - 4074;
        phase_wait(&g_pc[3], 1000);
        __shared__ int cand[256];
        __shared__ int cnt;
        __shared__ unsigned long long swr[8];
        __shared__ bool lastb;
        __shared__ int s_idx;
        __shared__ float s_tok;
        if (tid == 0) cnt = 0;
        __syncthreads();
        float lo = key_val(g_s.lomax);
        int r = rb * 256 + tid;
        if (__ldcg(&g_s.hi[r]) >= lo) cand[atomicAdd(&cnt, 1)] = r;
        __syncthreads();
        const float4* X = (const float4*)h3q;
        float4 x4c[8];
#pragma unroll
        for (int k = 0; k < 8; k++) x4c[k] = __ldcg(&X[lane + 32 * k]);
        unsigned long long rbest = 0ull;
        int n = cnt;
        for (int ci = wid; ci < n; ci += 8) {
            int row = cand[ci];
            const float4* Wr = (const float4*)(fcw32 + (size_t)row * Hdim);
            float d = 0.f;
#pragma unroll
            for (int k = 0; k < 8; k++) {
                float4 a = Wr[lane + 32 * k];
                d += a.x * x4c[k].x + a.y * x4c[k].y + a.z * x4c[k].z + a.w * x4c[k].w;
            }
            d = warp_sum(d);
            if (lane == 0) {
                unsigned long long key = packkey(d + fcb[row], (unsigned)row);
                if (key > rbest) rbest = key;
            }
        }
        if (lane == 0) swr[wid] = rbest;
        __syncthreads();
        if (tid == 0) {
            unsigned long long m = swr[0];
#pragma unroll
            for (int k = 1; k < 8; k++) if (swr[k] > m) m = swr[k];
            if (m) atomicMax(&g_s.exmax, m);
            __threadfence();
            lastb = (atomicAdd(&g_s.ticket3, 1u) == 124u);
        }
        __syncthreads();
        if (!lastb) return;

        if (tid == 0) {
            unsigned long long m = atomicAdd(&g_s.exmax, 0ull);
            s_idx = key_idx(m);
            s_tok = tot[s_idx];
            g_s.lomax = 0ull;
            g_s.exmax = 0ull;
            g_s.ticket3 = 0u;
            g_pc[0] = 0u; g_pc[1] = 0u; g_pc[2] = 0u; g_pc[3] = 0u;
        }
        __syncthreads();
        int idx = s_idx;
        ((float4*)g_s.word)[tid] = ((const float4*)(embed + (size_t)idx * Hdim))[tid];
        out[tid * Tlen + t] = s_tok;   // batch == 256 == blockDim
    }
}

extern "C" void kernel_launch(void* const* d_in, const int* in_sizes, int n_in,
                              void* d_out, int out_size) {
    const float* features  = (const float*)d_in[0];
    const float* fc1_w     = (const float*)d_in[1];
    const float* fc1_b     = (const float*)d_in[2];
    const float* init_h_w  = (const float*)d_in[3];
    const float* init_h_b  = (const float*)d_in[4];
    const float* init_c_w  = (const float*)d_in[5];
    const float* init_c_b  = (const float*)d_in[6];
    const float* ln_h_g    = (const float*)d_in[7];
    const float* ln_h_b    = (const float*)d_in[8];
    const float* ln_c_g    = (const float*)d_in[9];
    const float* ln_c_b    = (const float*)d_in[10];
    const float* w_ih1     = (const float*)d_in[11];
    const float* w_hh1     = (const float*)d_in[12];
    const float* b_ih1     = (const float*)d_in[13];
    const float* b_hh1     = (const float*)d_in[14];
    const float* w_ih2     = (const float*)d_in[15];
    const float* w_hh2     = (const float*)d_in[16];
    const float* b_ih2     = (const float*)d_in[17];
    const float* b_hh2     = (const float*)d_in[18];
    const float* fc_w      = (const float*)d_in[19];
    const float* fc_b      = (const float*)d_in[20];
    const float* embed_w   = (const float*)d_in[21];
    const float* totoken_w = (const float*)d_in[22];
    float* out = (float*)d_out;

    State* S = nullptr;
    cudaGetSymbolAddress((void**)&S, g_s);

    // prologue
    k_pro1<<<Hdim + Vdim / 8, 256>>>(features, fc1_w, fc1_b, fc_w);
    k_init2<<<2 * Hdim, 256>>>(init_h_w, init_h_b, init_c_w, init_c_b,
                               ln_h_g, ln_h_b, ln_c_g, ln_c_b);

    const int GRID = 4199;

    // step 0: cell1 inputs = feat/h/c; cells 2,3 recur against h/c
    k_step<<<GRID, 256>>>(
        S->feat, S->h, S->c,
        w_ih1, w_hh1, b_ih1, b_hh1, w_ih2, w_hh2, b_ih2, b_hh2,
        S->h, S->c, S->h, S->c,
        S->h2[0], S->c2[0], S->h3[0], S->c3[0],
        ln_h_g, ln_h_b, ln_c_g, ln_c_b,
        fc_b, fc_w, embed_w, totoken_w, out, 0);

    int p = 0;
    for (int t = 1; t < Tlen; t++) {
        int q = 1 - p;
        k_step<<<GRID, 256>>>(
            S->word, S->tmph, S->tmpc,
            w_ih1, w_hh1, b_ih1, b_hh1, w_ih2, w_hh2, b_ih2, b_hh2,
            S->h2[p], S->c2[p], S->h3[p], S->c3[p],
            S->h2[q], S->c2[q], S->h3[q], S->c3[q],
            ln_h_g, ln_h_b, ln_c_g, ln_c_b,
            fc_b, fc_w, embed_w, totoken_w, out, t);
        p = q;
    }
}

// round 12
// speedup vs baseline: 1.6275x; 1.6275x over previous
#include <cuda_runtime.h>
#include <cuda_bf16.h>
#include <cstdint>
#include <cstddef>

#define Hdim 1024
#define Edim 18432
#define Vdim 32000
#define Tlen 15

// k_fcr grid layout
#define NFC 1000                 // fcb8 blocks
#define NHH 1536                 // hh blocks (3 sets x 512)
#define NRF 125                  // refine blocks
#define GRID_FCR (NFC + NHH + NRF)

struct State {
    float feat[Hdim];
    float h[Hdim], c[Hdim];
    float tmph[Hdim], tmpc[Hdim];
    float h1[Hdim], c1[Hdim];
    float h2[2][Hdim], c2[2][Hdim];
    float h3[2][Hdim], c3[2][Hdim];
    float word[Hdim];
    float hi[Vdim];
    unsigned long long lomax, exmax;
    unsigned ticket1, ticket3, tickF;
};
__device__ State g_s;
__device__ unsigned g_fcw8[(size_t)Vdim * (Hdim / 4)];  // int8-packed fc_w (32.8 MB)
__device__ float g_scale[Vdim];
__device__ float g_sumw[Vdim];
__device__ float g_hhp[3][4 * Hdim];   // hh partials (+bhh) for cells 1..3 of next step

// ---------- helpers ----------
__device__ __forceinline__ float sigf(float x) { return 1.0f / (1.0f + expf(-x)); }

__device__ __forceinline__ float warp_sum(float s) {
#pragma unroll
    for (int o = 16; o; o >>= 1) s += __shfl_xor_sync(0xffffffffu, s, o);
    return s;
}
__device__ __forceinline__ int warp_isum(int s) {
#pragma unroll
    for (int o = 16; o; o >>= 1) s += __shfl_xor_sync(0xffffffffu, s, o);
    return s;
}
__device__ __forceinline__ float warp_max(float s) {
#pragma unroll
    for (int o = 16; o; o >>= 1) s = fmaxf(s, __shfl_xor_sync(0xffffffffu, s, o));
    return s;
}

__device__ __forceinline__ float block_sum(float s) {
    __shared__ float sm[8];
    __shared__ float outv;
    int w = threadIdx.x >> 5, lane = threadIdx.x & 31;
    s = warp_sum(s);
    if (lane == 0) sm[w] = s;
    __syncthreads();
    if (w == 0) {
        float r = (lane < 8) ? sm[lane] : 0.0f;
        r = warp_sum(r);
        if (lane == 0) outv = r;
    }
    __syncthreads();
    float res = outv;
    __syncthreads();
    return res;
}

__device__ __forceinline__ unsigned long long packkey(float v, unsigned idx) {
    unsigned u = __float_as_uint(v);
    u = (u & 0x80000000u) ? ~u : (u | 0x80000000u);
    return ((unsigned long long)u << 32) | (unsigned long long)(0xFFFFFFFFu - idx);
}
__device__ __forceinline__ float key_val(unsigned long long k) {
    unsigned u = (unsigned)(k >> 32);
    u = (u & 0x80000000u) ? (u ^ 0x80000000u) : ~u;
    return __uint_as_float(u);
}
__device__ __forceinline__ int key_idx(unsigned long long k) {
    return (int)(0xFFFFFFFFu - (unsigned)(k & 0xFFFFFFFFull));
}

__device__ __forceinline__ int clamp127(int q) {
    return q < -127 ? -127 : (q > 127 ? 127 : q);
}
__device__ __forceinline__ unsigned pack4(float4 f, float inv) {
    int a = clamp127(__float2int_rn(f.x * inv));
    int b = clamp127(__float2int_rn(f.y * inv));
    int c = clamp127(__float2int_rn(f.z * inv));
    int d = clamp127(__float2int_rn(f.w * inv));
    return (a & 0xFF) | ((b & 0xFF) << 8) | ((c & 0xFF) << 16) | ((d & 0xFF) << 24);
}

// ---------- LayerNorm by one 256-thread block ----------
__device__ void ln256(const float* __restrict__ x, const float* __restrict__ g,
                      const float* __restrict__ b, const float* __restrict__ base,
                      float* __restrict__ o) {
    float xv[4];
    float s = 0.f;
#pragma unroll
    for (int k = 0; k < 4; k++) { xv[k] = x[threadIdx.x + 256 * k]; s += xv[k]; }
    float m = block_sum(s) * (1.f / Hdim);
    float q = 0.f;
#pragma unroll
    for (int k = 0; k < 4; k++) { float d = xv[k] - m; q += d * d; }
    float v = block_sum(q) * (1.f / Hdim);
    float inv = rsqrtf(v + 1e-5f);
#pragma unroll
    for (int k = 0; k < 4; k++) {
        int i = threadIdx.x + 256 * k;
        float r = (xv[k] - m) * inv * g[i] + b[i];
        if (base) r += base[i];
        o[i] = r;
    }
}

// ---------- prologue: fc1 rows (blocks < Hdim) + int8 quantize fc_w (rest) ----------
__global__ void __launch_bounds__(256) k_pro1(
    const float* __restrict__ feats, const float* __restrict__ w,
    const float* __restrict__ bias, const float* __restrict__ fcw32) {
    int wid = threadIdx.x >> 5, lane = threadIdx.x & 31;
    if (blockIdx.x < Hdim) {
        int j = blockIdx.x;
        const float4* Wr = (const float4*)(w + (size_t)j * Edim);
        const float4* X  = (const float4*)feats;
        float s = 0.f;
        for (int i = threadIdx.x; i < Edim / 4; i += 256) {
            float4 a = __ldcs(&Wr[i]), v = X[i];
            s += a.x * v.x + a.y * v.y + a.z * v.z + a.w * v.w;
        }
        s = block_sum(s);
        if (threadIdx.x == 0) g_s.feat[j] = fmaxf(s + bias[j], 0.f);
    } else {
        int r = (blockIdx.x - Hdim) * 8 + wid;
        const float4* Wr = (const float4*)(fcw32 + (size_t)r * Hdim);
        float4 v[8];
        float ma = 0.f, sa = 0.f;
#pragma unroll
        for (int k = 0; k < 8; k++) {
            v[k] = __ldcs(&Wr[lane + 32 * k]);
            ma = fmaxf(ma, fmaxf(fmaxf(fabsf(v[k].x), fabsf(v[k].y)),
                                 fmaxf(fabsf(v[k].z), fabsf(v[k].w))));
            sa += fabsf(v[k].x) + fabsf(v[k].y) + fabsf(v[k].z) + fabsf(v[k].w);
        }
        ma = warp_max(ma);
        sa = warp_sum(sa);
        float mg = fmaxf(ma, 1e-30f);
        float s = mg * (1.f / 127.f);
        float inv = 127.f / mg;
        unsigned* W8 = g_fcw8 + (size_t)r * (Hdim / 4);
#pragma unroll
        for (int k = 0; k < 8; k++) W8[lane + 32 * k] = pack4(v[k], inv);
        if (lane == 0) { g_scale[r] = s; g_sumw[r] = sa; }
    }
}

// ---------- init h/c GEMVs + (last block) prologue LayerNorms ----------
__global__ void __launch_bounds__(256) k_init2(
    const float* __restrict__ wh, const float* __restrict__ bh,
    const float* __restrict__ wc, const float* __restrict__ bc,
    const float* __restrict__ lnhg, const float* __restrict__ lnhb,
    const float* __restrict__ lncg, const float* __restrict__ lncb) {
    int j = blockIdx.x;
    bool ish = j < Hdim;
    int r = ish ? j : j - Hdim;
    const float4* Wr = (const float4*)((ish ? wh : wc) + (size_t)r * Hdim);
    const float4* X  = (const float4*)g_s.feat;
    float4 a = __ldcs(&Wr[threadIdx.x]), v = X[threadIdx.x];
    float s = a.x * v.x + a.y * v.y + a.z * v.z + a.w * v.w;
    s = block_sum(s);
    __shared__ bool lastb;
    if (threadIdx.x == 0) {
        float val = fmaxf(s + (ish ? bh[r] : bc[r]), 0.f);
        if (ish) g_s.tmph[r] = val; else g_s.tmpc[r] = val;
        __threadfence();
        lastb = (atomicAdd(&g_s.ticket1, 1u) == 2u * Hdim - 1u);
    }
    __syncthreads();
    if (!lastb) return;
    ln256(g_s.tmph, lnhg, lnhb, nullptr, g_s.h);
    ln256(g_s.tmpc, lncg, lncb, nullptr, g_s.c);
    if (threadIdx.x == 0) g_s.ticket1 = 0;
}

// ---------- full LSTM cell (step 0 only; R7-proven) ----------
template <bool FUSELN>
__global__ void __launch_bounds__(256) k_cell(
    const float* __restrict__ x, const float* __restrict__ hin, const float* __restrict__ cin,
    const float* __restrict__ wih, const float* __restrict__ whh,
    const float* __restrict__ bih, const float* __restrict__ bhh,
    float* __restrict__ hout, float* __restrict__ cout,
    const float* __restrict__ lnhg, const float* __restrict__ lnhb,
    const float* __restrict__ lncg, const float* __restrict__ lncb) {
    if (FUSELN && blockIdx.x >= Hdim) {
        bool ish = (blockIdx.x == Hdim);
        ln256(ish ? g_s.h1 : g_s.c1,
              ish ? lnhg : lncg, ish ? lnhb : lncb,
              ish ? g_s.h : g_s.c,
              ish ? g_s.tmph : g_s.tmpc);
        return;
    }
    int j = blockIdx.x;
    int w = threadIdx.x >> 5, lane = threadIdx.x & 31;
    const float* Wm  = (w < 4) ? wih : whh;
    const float* vec = (w < 4) ? x : hin;
    int row = j + (w & 3) * Hdim;
    const float4* Wr = (const float4*)(Wm + (size_t)row * Hdim);
    const float4* v4 = (const float4*)vec;
    float s = 0.f;
#pragma unroll
    for (int i = 0; i < 8; i++) {
        float4 a = Wr[lane + 32 * i];
        float4 b = v4[lane + 32 * i];
        s += a.x * b.x + a.y * b.y + a.z * b.z + a.w * b.w;
    }
    s = warp_sum(s);
    __shared__ float red[8];
    if (lane == 0) red[w] = s;
    __syncthreads();
    if (threadIdx.x == 0) {
        float gi = red[0] + red[4] + bih[j]            + bhh[j];
        float gf = red[1] + red[5] + bih[j + Hdim]     + bhh[j + Hdim];
        float gg = red[2] + red[6] + bih[j + 2 * Hdim] + bhh[j + 2 * Hdim];
        float go = red[3] + red[7] + bih[j + 3 * Hdim] + bhh[j + 3 * Hdim];
        float cn = sigf(gf) * cin[j] + sigf(gi) * tanhf(gg);
        cout[j] = cn;
        hout[j] = sigf(go) * tanhf(cn);
    }
}

// ---------- hh-half GEMV body: g_hhp[set][g*H+j] = Whh[g*H+j,:]@hin + bhh[g*H+j] ----------
__device__ __forceinline__ void hh_body(int set, int b, const float* __restrict__ hin,
                                        const float* __restrict__ W,
                                        const float* __restrict__ bb) {
    int w = threadIdx.x >> 5, lane = threadIdx.x & 31;
    int g = w & 3, rl = w >> 2;
    int j = b * 2 + rl;
    int row = g * Hdim + j;
    const float4* Wr = (const float4*)(W + (size_t)row * Hdim);
    const float4* v4 = (const float4*)hin;
    float s = 0.f;
#pragma unroll
    for (int i = 0; i < 8; i++) {
        float4 a = Wr[lane + 32 * i];
        float4 vb = v4[lane + 32 * i];
        s += a.x * vb.x + a.y * vb.y + a.z * vb.z + a.w * vb.w;
    }
    s = warp_sum(s);
    if (lane == 0) g_hhp[set][row] = s + bb[row];
}

// ---------- combine: ih-half GEMV + hh partial + pointwise. 512 blocks, 2 rows each ----------
template <bool FUSELN>
__global__ void __launch_bounds__(256) k_comb(
    const float* __restrict__ x, const float* __restrict__ cin, int set,
    const float* __restrict__ wih, const float* __restrict__ bih,
    float* __restrict__ hout, float* __restrict__ cout,
    const float* __restrict__ lnhg, const float* __restrict__ lnhb,
    const float* __restrict__ lncg, const float* __restrict__ lncb) {
    if (FUSELN && blockIdx.x >= 512) {
        bool ish = (blockIdx.x == 512);
        ln256(ish ? g_s.h1 : g_s.c1,
              ish ? lnhg : lncg, ish ? lnhb : lncb,
              ish ? g_s.h : g_s.c,
              ish ? g_s.tmph : g_s.tmpc);
        return;
    }
    int tid = threadIdx.x;
    int w = tid >> 5, lane = tid & 31;
    int g = w & 3, rl = w >> 2;
    int j = blockIdx.x * 2 + rl;
    int row = g * Hdim + j;
    const float4* Wr = (const float4*)(wih + (size_t)row * Hdim);
    const float4* v4 = (const float4*)x;
    float s = 0.f;
#pragma unroll
    for (int i = 0; i < 8; i++) {
        float4 a = Wr[lane + 32 * i];
        float4 vb = v4[lane + 32 * i];
        s += a.x * vb.x + a.y * vb.y + a.z * vb.z + a.w * vb.w;
    }
    s = warp_sum(s);
    __shared__ float red[8];
    if (lane == 0) red[w] = s + bih[row] + g_hhp[set][row];
    __syncthreads();
    if (tid == 0 || tid == 128) {
        int rr = tid >> 7;
        int jj = blockIdx.x * 2 + rr;
        float gi = red[rr * 4 + 0], gf = red[rr * 4 + 1];
        float gg = red[rr * 4 + 2], go = red[rr * 4 + 3];
        float cn = sigf(gf) * cin[jj] + sigf(gi) * tanhf(gg);
        cout[jj] = cn;
        hout[jj] = sigf(go) * tanhf(cn);
    }
}

// ---------- mega-kernel: fcb8 + next-step hh GEMVs + refine, one launch ----------
// [0,NFC): fcb8; [NFC,NFC+NHH): hh (independent; inputs ready at launch);
// [NFC+NHH,GRID): refine — only these spin, and only on fcb8 (deadlock-free).
__global__ void __launch_bounds__(256) k_fcr(
    const float* __restrict__ x,       // = h3 current
    const float* __restrict__ h2cur,
    const float* __restrict__ w_hh1, const float* __restrict__ w_hh2,
    const float* __restrict__ b_hh1, const float* __restrict__ b_hh2,
    const float* __restrict__ fcb, const float* __restrict__ fcw32,
    const float* __restrict__ embed, const float* __restrict__ tot,
    float* __restrict__ out, int t, int do_hh) {
    int bid = blockIdx.x;
    int tid = threadIdx.x, wid = tid >> 5, lane = tid & 31;
    const float4* X = (const float4*)x;

    if (bid < NFC) {   // ---- fcb8 ----
        float4 xv[8];
        float ma = 0.f, sa = 0.f;
#pragma unroll
        for (int k = 0; k < 8; k++) {
            xv[k] = X[lane + 32 * k];
            ma = fmaxf(ma, fmaxf(fmaxf(fabsf(xv[k].x), fabsf(xv[k].y)),
                                 fmaxf(fabsf(xv[k].z), fabsf(xv[k].w))));
            sa += fabsf(xv[k].x) + fabsf(xv[k].y) + fabsf(xv[k].z) + fabsf(xv[k].w);
        }
        ma = warp_max(ma);
        float sumAbsX = warp_sum(sa);
        float mg = fmaxf(ma, 1e-30f);
        float sx = mg * (1.f / 127.f);
        float invx = 127.f / mg;
        unsigned qx[8];
#pragma unroll
        for (int k = 0; k < 8; k++) qx[k] = pack4(xv[k], invx);
        unsigned long long wbest = 0ull;
        int r0 = (bid * 8 + wid) * 4;
#pragma unroll
        for (int rr = 0; rr < 4; rr++) {
            int r = r0 + rr;
            const unsigned* W8 = g_fcw8 + (size_t)r * (Hdim / 4);
            int acc = 0;
#pragma unroll
            for (int k = 0; k < 8; k++)
                acc = __dp4a((int)W8[lane + 32 * k], (int)qx[k], acc);
            acc = warp_isum(acc);
            if (lane == 0) {
                float sr = g_scale[r];
                float v = sr * sx * (float)acc + fcb[r];
                float err = (0.5f * sx * g_sumw[r] + 0.5f * sr * (sumAbsX + 512.f * sx)) * 1.1f
                            + 1e-7f;
                g_s.hi[r] = v + err;
                unsigned long long key = packkey(v - err, (unsigned)r);
                if (key > wbest) wbest = key;
            }
        }
        __shared__ unsigned long long sb[8];
        if (lane == 0) sb[wid] = wbest;
        __syncthreads();
        if (tid == 0) {
            unsigned long long m = sb[0];
#pragma unroll
            for (int k = 1; k < 8; k++) if (sb[k] > m) m = sb[k];
            atomicMax(&g_s.lomax, m);
            __threadfence();
            atomicAdd(&g_s.tickF, 1u);
        }
        return;
    }

    if (bid < NFC + NHH) {   // ---- hh GEMVs for the next step ----
        if (do_hh) {
            int local = bid - NFC;
            int set = local >> 9, b = local & 511;
            const float* hin = (set == 0) ? g_s.tmph : ((set == 1) ? h2cur : x);
            const float* W   = (set == 0) ? w_hh1 : w_hh2;
            const float* bb  = (set == 0) ? b_hh1 : b_hh2;
            hh_body(set, b, hin, W, bb);
        }
        return;
    }

    // ---- refine (NRF blocks; spin until all fcb8 blocks done) ----
    if (tid == 0) {
        volatile unsigned* vc = &g_s.tickF;
        while (*vc < (unsigned)NFC) __nanosleep(64);
    }
    __syncthreads();
    int rb = bid - (NFC + NHH);
    __shared__ int cand[256];
    __shared__ int cnt;
    __shared__ unsigned long long swr[8];
    __shared__ bool lastb;
    __shared__ int s_idx;
    __shared__ float s_tok;
    if (tid == 0) cnt = 0;
    __syncthreads();
    float lo = key_val(g_s.lomax);
    int r = rb * 256 + tid;
    if (__ldcg(&g_s.hi[r]) >= lo) cand[atomicAdd(&cnt, 1)] = r;
    __syncthreads();
    float4 x4c[8];
#pragma unroll
    for (int k = 0; k < 8; k++) x4c[k] = X[lane + 32 * k];
    unsigned long long rbest = 0ull;
    int n = cnt;
    for (int ci = wid; ci < n; ci += 8) {
        int row = cand[ci];
        const float4* Wr = (const float4*)(fcw32 + (size_t)row * Hdim);
        float d = 0.f;
#pragma unroll
        for (int k = 0; k < 8; k++) {
            float4 a = Wr[lane + 32 * k];
            d += a.x * x4c[k].x + a.y * x4c[k].y + a.z * x4c[k].z + a.w * x4c[k].w;
        }
        d = warp_sum(d);
        if (lane == 0) {
            unsigned long long key = packkey(d + fcb[row], (unsigned)row);
            if (key > rbest) rbest = key;
        }
    }
    if (lane == 0) swr[wid] = rbest;
    __syncthreads();
    if (tid == 0) {
        unsigned long long m = swr[0];
#pragma unroll
        for (int k = 1; k < 8; k++) if (swr[k] > m) m = swr[k];
        if (m) atomicMax(&g_s.exmax, m);
        __threadfence();
        lastb = (atomicAdd(&g_s.ticket3, 1u) == NRF - 1u);
    }
    __syncthreads();
    if (!lastb) return;

    if (tid == 0) {
        unsigned long long m = atomicAdd(&g_s.exmax, 0ull);
        s_idx = key_idx(m);
        s_tok = tot[s_idx];
        g_s.lomax = 0ull;
        g_s.exmax = 0ull;
        g_s.ticket3 = 0u;
        g_s.tickF = 0u;
    }
    __syncthreads();
    int idx = s_idx;
    ((float4*)g_s.word)[tid] = ((const float4*)(embed + (size_t)idx * Hdim))[tid];
    out[tid * Tlen + t] = s_tok;   // batch == 256 == blockDim
}

extern "C" void kernel_launch(void* const* d_in, const int* in_sizes, int n_in,
                              void* d_out, int out_size) {
    const float* features  = (const float*)d_in[0];
    const float* fc1_w     = (const float*)d_in[1];
    const float* fc1_b     = (const float*)d_in[2];
    const float* init_h_w  = (const float*)d_in[3];
    const float* init_h_b  = (const float*)d_in[4];
    const float* init_c_w  = (const float*)d_in[5];
    const float* init_c_b  = (const float*)d_in[6];
    const float* ln_h_g    = (const float*)d_in[7];
    const float* ln_h_b    = (const float*)d_in[8];
    const float* ln_c_g    = (const float*)d_in[9];
    const float* ln_c_b    = (const float*)d_in[10];
    const float* w_ih1     = (const float*)d_in[11];
    const float* w_hh1     = (const float*)d_in[12];
    const float* b_ih1     = (const float*)d_in[13];
    const float* b_hh1     = (const float*)d_in[14];
    const float* w_ih2     = (const float*)d_in[15];
    const float* w_hh2     = (const float*)d_in[16];
    const float* b_ih2     = (const float*)d_in[17];
    const float* b_hh2     = (const float*)d_in[18];
    const float* fc_w      = (const float*)d_in[19];
    const float* fc_b      = (const float*)d_in[20];
    const float* embed_w   = (const float*)d_in[21];
    const float* totoken_w = (const float*)d_in[22];
    float* out = (float*)d_out;

    State* S = nullptr;
    cudaGetSymbolAddress((void**)&S, g_s);
    const float* FN = nullptr;

    // prologue
    k_pro1<<<Hdim + Vdim / 8, 256>>>(features, fc1_w, fc1_b, fc_w);
    k_init2<<<2 * Hdim, 256>>>(init_h_w, init_h_b, init_c_w, init_c_b,
                               ln_h_g, ln_h_b, ln_c_g, ln_c_b);

    // ---- step 0: full cells (R7 path) then fcr (with hh for step 1) ----
    k_cell<false><<<Hdim, 256>>>(S->feat, S->h, S->c,
        w_ih1, w_hh1, b_ih1, b_hh1, S->h1, S->c1, FN, FN, FN, FN);
    k_cell<true><<<Hdim + 2, 256>>>(S->h1, S->h, S->c,
        w_ih2, w_hh2, b_ih2, b_hh2, S->h2[0], S->c2[0],
        ln_h_g, ln_h_b, ln_c_g, ln_c_b);
    k_cell<false><<<Hdim, 256>>>(S->h2[0], S->h, S->c,
        w_ih2, w_hh2, b_ih2, b_hh2, S->h3[0], S->c3[0], FN, FN, FN, FN);
    k_fcr<<<GRID_FCR, 256>>>(S->h3[0], S->h2[0],
        w_hh1, w_hh2, b_hh1, b_hh2,
        fc_b, fc_w, embed_w, totoken_w, out, 0, 1);

    // ---- steps 1..14: slim ih-combine chain + fused hh in fcr ----
    for (int t = 1; t < Tlen; t++) {
        int q = t & 1, p = q ^ 1;
        k_comb<false><<<512, 256>>>(S->word, S->tmpc, 0, w_ih1, b_ih1,
                                    S->h1, S->c1, FN, FN, FN, FN);
        k_comb<true><<<514, 256>>>(S->h1, S->c2[p], 1, w_ih2, b_ih2,
                                   S->h2[q], S->c2[q],
                                   ln_h_g, ln_h_b, ln_c_g, ln_c_b);
        k_comb<false><<<512, 256>>>(S->h2[q], S->c3[p], 2, w_ih2, b_ih2,
                                    S->h3[q], S->c3[q], FN, FN, FN, FN);
        k_fcr<<<GRID_FCR, 256>>>(S->h3[q], S->h2[q],
            w_hh1, w_hh2, b_hh1, b_hh2,
            fc_b, fc_w, embed_w, totoken_w, out, t, (t < Tlen - 1) ? 1 : 0);
    }
}